// round 2
// baseline (speedup 1.0000x reference)
#include <cuda_runtime.h>
#include <math.h>

#define T_ 128
#define B_ 128
#define I_ 256
#define H_ 256
#define G4_ 1024

__device__ float g_preact[(size_t)T_ * B_ * G4_];
__device__ float g_c[B_ * H_];

// Phase 1: preact[t] = x[t]@Wi[t] + bi[t] + bh[t].  Grid (8, T), 256 thr.
__global__ __launch_bounds__(256) void lstm_phase1(
    const float* __restrict__ x, const float* __restrict__ Wi,
    const float* __restrict__ bi, const float* __restrict__ bh,
    float* __restrict__ preact)
{
    __shared__ float As[2][16][128];
    __shared__ float Bs[2][16][128];

    const int t = blockIdx.y, n0 = blockIdx.x * 128, tid = threadIdx.x;
    const int tx = tid & 15, ty = tid >> 4;
    const float* xA = x + (size_t)t * (B_ * I_);
    const float* WB = Wi + (size_t)t * (I_ * G4_) + n0;
    const int am = tid >> 1, aq = (tid & 1) * 2;
    const int bk = tid >> 4, bn = (tid & 15) * 4;

    float acc[8][8];
#pragma unroll
    for (int i = 0; i < 8; ++i)
#pragma unroll
        for (int j = 0; j < 8; ++j) acc[i][j] = 0.f;

    {
        float4 a0 = *(const float4*)(xA + am * I_ + (aq + 0) * 4);
        float4 a1 = *(const float4*)(xA + am * I_ + (aq + 1) * 4);
        As[0][aq * 4 + 0][am] = a0.x; As[0][aq * 4 + 1][am] = a0.y;
        As[0][aq * 4 + 2][am] = a0.z; As[0][aq * 4 + 3][am] = a0.w;
        As[0][aq * 4 + 4][am] = a1.x; As[0][aq * 4 + 5][am] = a1.y;
        As[0][aq * 4 + 6][am] = a1.z; As[0][aq * 4 + 7][am] = a1.w;
        *(float4*)&Bs[0][bk][bn]      = *(const float4*)(WB + (size_t)bk * G4_ + bn);
        *(float4*)&Bs[0][bk][bn + 64] = *(const float4*)(WB + (size_t)bk * G4_ + bn + 64);
    }
    __syncthreads();

    for (int kt = 0; kt < 16; ++kt) {
        const int cur = kt & 1;
        float4 pa0, pa1, pb0, pb1;
        if (kt < 15) {
            const int k0 = (kt + 1) * 16;
            pa0 = *(const float4*)(xA + am * I_ + k0 + (aq + 0) * 4);
            pa1 = *(const float4*)(xA + am * I_ + k0 + (aq + 1) * 4);
            pb0 = *(const float4*)(WB + (size_t)(k0 + bk) * G4_ + bn);
            pb1 = *(const float4*)(WB + (size_t)(k0 + bk) * G4_ + bn + 64);
        }
#pragma unroll
        for (int kk = 0; kk < 16; ++kk) {
            float4 a0 = *(float4*)&As[cur][kk][ty * 4];
            float4 a1 = *(float4*)&As[cur][kk][64 + ty * 4];
            float4 b0 = *(float4*)&Bs[cur][kk][tx * 4];
            float4 b1 = *(float4*)&Bs[cur][kk][64 + tx * 4];
            float av[8] = {a0.x, a0.y, a0.z, a0.w, a1.x, a1.y, a1.z, a1.w};
            float bv[8] = {b0.x, b0.y, b0.z, b0.w, b1.x, b1.y, b1.z, b1.w};
#pragma unroll
            for (int i = 0; i < 8; ++i)
#pragma unroll
                for (int j = 0; j < 8; ++j) acc[i][j] += av[i] * bv[j];
        }
        if (kt < 15) {
            const int nb = cur ^ 1;
            As[nb][aq * 4 + 0][am] = pa0.x; As[nb][aq * 4 + 1][am] = pa0.y;
            As[nb][aq * 4 + 2][am] = pa0.z; As[nb][aq * 4 + 3][am] = pa0.w;
            As[nb][aq * 4 + 4][am] = pa1.x; As[nb][aq * 4 + 5][am] = pa1.y;
            As[nb][aq * 4 + 6][am] = pa1.z; As[nb][aq * 4 + 7][am] = pa1.w;
            *(float4*)&Bs[nb][bk][bn]      = pb0;
            *(float4*)&Bs[nb][bk][bn + 64] = pb1;
            __syncthreads();
        }
    }

    const float* bip = bi + (size_t)t * G4_ + n0;
    const float* bhp = bh + (size_t)t * G4_ + n0;
    float* Cp = preact + (size_t)t * (B_ * G4_) + n0;
    float4 i0 = *(const float4*)(bip + tx * 4);
    float4 h0 = *(const float4*)(bhp + tx * 4);
    float4 i1 = *(const float4*)(bip + 64 + tx * 4);
    float4 h1 = *(const float4*)(bhp + 64 + tx * 4);
    float bs[8] = {i0.x + h0.x, i0.y + h0.y, i0.z + h0.z, i0.w + h0.w,
                   i1.x + h1.x, i1.y + h1.y, i1.z + h1.z, i1.w + h1.w};
#pragma unroll
    for (int i = 0; i < 8; ++i) {
        const int m = (i < 4) ? (ty * 4 + i) : (64 + ty * 4 + (i - 4));
        float4 v0 = make_float4(acc[i][0] + bs[0], acc[i][1] + bs[1],
                                acc[i][2] + bs[2], acc[i][3] + bs[3]);
        float4 v1 = make_float4(acc[i][4] + bs[4], acc[i][5] + bs[5],
                                acc[i][6] + bs[6], acc[i][7] + bs[7]);
        *(float4*)(Cp + (size_t)m * G4_ + tx * 4)      = v0;
        *(float4*)(Cp + (size_t)m * G4_ + 64 + tx * 4) = v1;
    }
}

// Phase 2: one kernel per timestep, fused gemm + cell update.
// Grid (32 hcol-groups, 4 row-groups), 256 thr. CTA: 32 rows x 8 hcols x 4 gates.
__global__ __launch_bounds__(256) void lstm_step(
    const float* __restrict__ hprev, const float* __restrict__ cprev,
    const float* __restrict__ Wht, const float* __restrict__ pre,
    float* __restrict__ hout, float* __restrict__ cout)
{
    __shared__ float Hs[128][36];
    __shared__ float Ws[128][32];

    const int tid = threadIdx.x;
    const int oc = tid & 31;      // gate g = oc>>3, col c = oc&7
    const int rq = tid >> 5;      // row quad 0..7
    const int hc0 = blockIdx.x * 8;
    const int r0 = blockIdx.y * 32;

    float acc[4] = {0.f, 0.f, 0.f, 0.f};

    for (int kh = 0; kh < 2; ++kh) {
        const int kb = kh * 128;
#pragma unroll
        for (int i2 = 0; i2 < 16; ++i2) {
            const int s = i2 * 256 + tid;
            Hs[s & 127][s >> 7] = hprev[(r0 + (s >> 7)) * H_ + kb + (s & 127)];
        }
#pragma unroll
        for (int i2 = 0; i2 < 4; ++i2) {
            const int idx = i2 * 256 + tid;
            const int k = idx >> 3, q = idx & 7;
            const int g = q >> 1, c4 = (q & 1) * 4;
            *(float4*)&Ws[k][q * 4] =
                *(const float4*)(Wht + (size_t)(kb + k) * G4_ + g * 256 + hc0 + c4);
        }
        __syncthreads();
#pragma unroll 16
        for (int kk = 0; kk < 128; ++kk) {
            float4 hv = *(const float4*)&Hs[kk][rq * 4];
            float  w  = Ws[kk][oc];
            acc[0] += hv.x * w; acc[1] += hv.y * w;
            acc[2] += hv.z * w; acc[3] += hv.w * w;
        }
        __syncthreads();
    }

    float* gsm = &Hs[0][0];  // reuse as [32 rows][32 oc]
    {
        const int g = oc >> 3, c = oc & 7;
        const int n = g * 256 + hc0 + c;
#pragma unroll
        for (int e = 0; e < 4; ++e) {
            const int r = rq * 4 + e;
            gsm[r * 32 + oc] = acc[e] + pre[(size_t)(r0 + r) * G4_ + n];
        }
    }
    __syncthreads();
    {
        const int r = tid >> 3, c2 = tid & 7;
        const float iv = gsm[r * 32 +  0 + c2];
        const float fv = gsm[r * 32 +  8 + c2];
        const float ov = gsm[r * 32 + 16 + c2];
        const float gv = gsm[r * 32 + 24 + c2];
        const int row = r0 + r, col = hc0 + c2;
        const float cp = cprev[row * H_ + col];
        const float ig = 1.f / (1.f + expf(-iv));
        const float fg = 1.f / (1.f + expf(-fv));
        const float og = 1.f / (1.f + expf(-ov));
        const float gt = tanhf(gv);
        const float cn = fg * cp + ig * gt;
        cout[row * H_ + col] = cn;
        hout[row * H_ + col] = og * tanhf(cn);
    }
}

extern "C" void kernel_launch(void* const* d_in, const int* in_sizes, int n_in,
                              void* d_out, int out_size)
{
    (void)in_sizes; (void)n_in; (void)out_size;
    const float* x   = (const float*)d_in[0];  // [T,B,I]
    const float* h0  = (const float*)d_in[1];  // [B,H]
    const float* c0  = (const float*)d_in[2];  // [B,H]
    const float* Wi  = (const float*)d_in[3];  // [T,I,4H]
    const float* bi  = (const float*)d_in[4];  // [T,4H]
    const float* Wh  = (const float*)d_in[5];  // [T,H,4H]
    const float* bh  = (const float*)d_in[6];  // [T,4H]

    float* out     = (float*)d_out;
    float* outputs = out;                          // [T,B,H]
    float* hfin    = out + (size_t)T_ * B_ * H_;   // [B,H]
    float* cfin    = hfin + (size_t)B_ * H_;       // [B,H]

    float* pre; float* cbuf;
    cudaGetSymbolAddress((void**)&pre,  g_preact);
    cudaGetSymbolAddress((void**)&cbuf, g_c);

    dim3 g1(8, T_);
    lstm_phase1<<<g1, 256>>>(x, Wi, bi, bh, pre);

    dim3 g2(32, 4);
    for (int t = 0; t < T_; ++t) {
        const float* hp = (t == 0) ? h0 : (outputs + (size_t)(t - 1) * B_ * H_);
        const float* cp = (t == 0) ? c0 : cbuf;
        lstm_step<<<g2, 256>>>(hp, cp,
                               Wh + (size_t)t * H_ * G4_,
                               pre + (size_t)t * B_ * G4_,
                               outputs + (size_t)t * B_ * H_,
                               cbuf);
    }

    cudaMemcpyAsync(hfin, outputs + (size_t)(T_ - 1) * B_ * H_,
                    (size_t)B_ * H_ * sizeof(float), cudaMemcpyDeviceToDevice);
    cudaMemcpyAsync(cfin, cbuf,
                    (size_t)B_ * H_ * sizeof(float), cudaMemcpyDeviceToDevice);
}